// round 2
// baseline (speedup 1.0000x reference)
#include <cuda_runtime.h>

#define NODES 100000
#define NEDGES 3200000
#define DD 20

// ---------------- static device scratch (no allocations allowed) ----------------
__device__ int   d_icnt[NODES];
__device__ int   d_ocnt[NODES];
__device__ int   d_rowptr[NODES + 1];
__device__ int   d_cursor[NODES];
__device__ int   d_col[NEDGES];
__device__ float d_din[NODES];
__device__ float d_dout[NODES];
__device__ float d_g0[NODES];
__device__ float d_gA[NODES * DD];
__device__ float d_gB[NODES * DD];

// ---------------- graph build ----------------
__global__ void k_zero() {
    int i = blockIdx.x * blockDim.x + threadIdx.x;
    if (i < NODES) { d_icnt[i] = 0; d_ocnt[i] = 0; }
}

__global__ void k_hist(const int* __restrict__ src, const int* __restrict__ dst) {
    int e = blockIdx.x * blockDim.x + threadIdx.x;
    if (e < NEDGES) {
        atomicAdd(&d_ocnt[src[e]], 1);
        atomicAdd(&d_icnt[dst[e]], 1);
    }
}

// exclusive scan of d_icnt -> d_rowptr (single block, chunked)
__global__ void k_scan() {
    __shared__ int part[1024];
    const int CH = (NODES + 1023) / 1024;  // 98
    int tid = threadIdx.x;
    int s0 = tid * CH;
    int s1 = s0 + CH; if (s1 > NODES) s1 = NODES; if (s0 > NODES) s0 = NODES;
    int sum = 0;
    for (int i = s0; i < s1; i++) sum += d_icnt[i];
    part[tid] = sum;
    __syncthreads();
    for (int off = 1; off < 1024; off <<= 1) {
        int v = (tid >= off) ? part[tid - off] : 0;
        __syncthreads();
        part[tid] += v;
        __syncthreads();
    }
    int run = (tid > 0) ? part[tid - 1] : 0;
    for (int i = s0; i < s1; i++) { d_rowptr[i] = run; run += d_icnt[i]; }
    if (tid == 1023) d_rowptr[NODES] = part[1023];
}

__global__ void k_init(const float* __restrict__ feat) {
    int i = blockIdx.x * blockDim.x + threadIdx.x;
    if (i < NODES) {
        float di = rsqrtf((float)(d_icnt[i] + 1));   // +1 self-loop, always >= 1
        float dq = rsqrtf((float)(d_ocnt[i] + 1));
        d_din[i] = di;
        d_dout[i] = dq;
        d_cursor[i] = d_rowptr[i];
        d_g0[i] = feat[i] * dq;                      // layer-0 source values (scalar)
    }
}

__global__ void k_scatter(const int* __restrict__ src, const int* __restrict__ dst) {
    int e = blockIdx.x * blockDim.x + threadIdx.x;
    if (e < NEDGES) {
        int p = atomicAdd(&d_cursor[dst[e]], 1);
        d_col[p] = src[e];
    }
}

// ---------------- layer 0 : scalar aggregation, D_in = 1 ----------------
__global__ void k_layer0(const float* __restrict__ W, const float* __restrict__ b) {
    const unsigned FULL = 0xffffffffu;
    int lane = threadIdx.x & 31;
    int w    = (blockIdx.x * blockDim.x + threadIdx.x) >> 5;
    int nw   = (gridDim.x * blockDim.x) >> 5;
    int tt   = lane < DD ? lane : 0;
    float wt = W[tt];
    float bt = b[tt];
    for (int n = w; n < NODES; n += nw) {
        int beg = d_rowptr[n], end = d_rowptr[n + 1];
        float acc = (lane == 0) ? d_g0[n] : 0.f;     // self-loop
        for (int j = beg + lane; j < end; j += 32)
            acc += __ldg(&d_g0[__ldg(&d_col[j])]);
        #pragma unroll
        for (int off = 16; off; off >>= 1)
            acc += __shfl_xor_sync(FULL, acc, off);
        if (lane < DD) {
            float r = fmaf(d_din[n] * acc, wt, bt);
            r = fmaxf(r, 0.f);
            d_gA[n * DD + lane] = r * d_dout[n];     // store g = h * dout
        }
    }
}

// ---------------- fused layer: aggregate(g) -> @W -> *din +b -> (relu) -> (*dout) ----
template <int RELU, int SCALE>
__device__ __forceinline__ void layer_body(const float* __restrict__ gin,
                                           float* __restrict__ gout,
                                           const float* __restrict__ W,
                                           const float* __restrict__ b) {
    const unsigned FULL = 0xffffffffu;
    int lane = threadIdx.x & 31;
    int w    = (blockIdx.x * blockDim.x + threadIdx.x) >> 5;
    int nw   = (gridDim.x * blockDim.x) >> 5;
    // lane layout for aggregation: 6 edges x 5 float4 chunks (lanes 30,31 idle)
    int c    = lane % 5;
    int esub = lane / 5;
    bool lok = lane < 30;
    // W column for matvec, loaded ONCE per warp lifetime (grid-stride amortizes it)
    int tt = lane < DD ? lane : 0;
    float wcol[DD];
    #pragma unroll
    for (int k = 0; k < DD; k++) wcol[k] = W[k * DD + tt];
    float bt = b[tt];
    const float4* gin4 = (const float4*)gin;

    for (int n = w; n < NODES; n += nw) {
        int beg = d_rowptr[n], end = d_rowptr[n + 1];
        float4 acc = make_float4(0.f, 0.f, 0.f, 0.f);
        if (lok && esub == 0) acc = __ldg(&gin4[n * 5 + c]);   // self-loop
        #pragma unroll 2
        for (int j0 = beg; j0 < end; j0 += 6) {
            int j = j0 + esub;
            if (lok && j < end) {
                int s = __ldg(&d_col[j]);
                float4 x = __ldg(&gin4[s * 5 + c]);
                acc.x += x.x; acc.y += x.y; acc.z += x.z; acc.w += x.w;
            }
        }
        // Reduce the 6 edge groups (stride 5). Predicated folds so already-consumed
        // lanes are never updated again (avoids double-count contamination):
        //   step1: lanes 0..14  += lanes 15..29   (g_i += g_{i+3})
        //   step2: lanes 0..4   += lanes 10..14   (clean g2+g5)
        //   step3: lanes 0..4   += lanes 5..9     (clean g1+g4, untouched by step2)
        float4 t;
        t.x = __shfl_down_sync(FULL, acc.x, 15);
        t.y = __shfl_down_sync(FULL, acc.y, 15);
        t.z = __shfl_down_sync(FULL, acc.z, 15);
        t.w = __shfl_down_sync(FULL, acc.w, 15);
        if (lane < 15) { acc.x += t.x; acc.y += t.y; acc.z += t.z; acc.w += t.w; }
        t.x = __shfl_down_sync(FULL, acc.x, 10);
        t.y = __shfl_down_sync(FULL, acc.y, 10);
        t.z = __shfl_down_sync(FULL, acc.z, 10);
        t.w = __shfl_down_sync(FULL, acc.w, 10);
        if (lane < 5) { acc.x += t.x; acc.y += t.y; acc.z += t.z; acc.w += t.w; }
        t.x = __shfl_down_sync(FULL, acc.x, 5);
        t.y = __shfl_down_sync(FULL, acc.y, 5);
        t.z = __shfl_down_sync(FULL, acc.z, 5);
        t.w = __shfl_down_sync(FULL, acc.w, 5);
        if (lane < 5) { acc.x += t.x; acc.y += t.y; acc.z += t.z; acc.w += t.w; }
        // lane c (c=0..4) now holds s[4c..4c+3]; broadcast + matvec out[tt] = sum_k s[k]*W[k][tt]
        float m = 0.f;
        #pragma unroll
        for (int k = 0; k < DD; k++) {
            float comp = ((k & 3) == 0) ? acc.x :
                         ((k & 3) == 1) ? acc.y :
                         ((k & 3) == 2) ? acc.z : acc.w;
            float sk = __shfl_sync(FULL, comp, k >> 2);
            m = fmaf(sk, wcol[k], m);
        }
        if (lane < DD) {
            float r = fmaf(d_din[n], m, bt);
            if (RELU)  r = fmaxf(r, 0.f);
            if (SCALE) r *= d_dout[n];
            gout[n * DD + lane] = r;
        }
    }
}

__global__ void k_layer_mid(const float* __restrict__ W, const float* __restrict__ b, int cur) {
    const float* gin = cur ? d_gB : d_gA;
    float* gout      = cur ? d_gA : d_gB;
    layer_body<1, 1>(gin, gout, W, b);
}

__global__ void k_layer_final(const float* __restrict__ W, const float* __restrict__ b,
                              int cur, float* __restrict__ out) {
    const float* gin = cur ? d_gB : d_gA;
    layer_body<0, 0>(gin, out, W, b);
}

// ---------------- launch ----------------
extern "C" void kernel_launch(void* const* d_in, const int* in_sizes, int n_in,
                              void* d_out, int out_size) {
    const float* feat = (const float*)d_in[0];
    const float* Ws   = (const float*)d_in[1];
    const float* bs   = (const float*)d_in[2];
    const float* Wm   = (const float*)d_in[3];
    const float* bm   = (const float*)d_in[4];
    const float* Wf   = (const float*)d_in[5];
    const float* bf   = (const float*)d_in[6];
    const int*   src  = (const int*)d_in[7];
    const int*   dst  = (const int*)d_in[8];
    float* out = (float*)d_out;

    // graph build (per-launch; CSR grouped by dst, self-loops kept implicit)
    k_zero   <<<(NODES  + 255) / 256, 256>>>();
    k_hist   <<<(NEDGES + 255) / 256, 256>>>(src, dst);
    k_scan   <<<1, 1024>>>();
    k_init   <<<(NODES  + 255) / 256, 256>>>(feat);
    k_scatter<<<(NEDGES + 255) / 256, 256>>>(src, dst);

    // 20 conv layers, one fused kernel each
    k_layer0<<<592, 256>>>(Ws, bs);                  // writes d_gA
    int cur = 0;                                      // 0: current in gA
    for (int k = 0; k < 18; k++) {
        k_layer_mid<<<592, 256>>>(Wm + k * DD * DD, bm + k * DD, cur);
        cur ^= 1;
    }
    k_layer_final<<<592, 256>>>(Wf, bf, cur, out);
}

// round 3
// speedup vs baseline: 1.0305x; 1.0305x over previous
#include <cuda_runtime.h>

#define NODES 100000
#define NEDGES 3200000
#define DD 20

// ---------------- static device scratch (no allocations allowed) ----------------
__device__ int   d_icnt[NODES];
__device__ int   d_ocnt[NODES];
__device__ int   d_rowptr[NODES + 1];
__device__ int   d_cursor[NODES];
__device__ int   d_col[NEDGES];
__device__ float d_din[NODES];
__device__ float d_dout[NODES];
__device__ float d_g0[NODES];
__device__ float d_gA[NODES * DD];
__device__ float d_gB[NODES * DD];

// ---------------- graph build ----------------
__global__ void k_zero() {
    int i = blockIdx.x * blockDim.x + threadIdx.x;
    if (i < NODES) { d_icnt[i] = 0; d_ocnt[i] = 0; }
}

__global__ void k_hist(const int* __restrict__ src, const int* __restrict__ dst) {
    int e = blockIdx.x * blockDim.x + threadIdx.x;
    if (e < NEDGES) {
        atomicAdd(&d_ocnt[src[e]], 1);
        atomicAdd(&d_icnt[dst[e]], 1);
    }
}

// exclusive scan of d_icnt -> d_rowptr (single block, chunked)
__global__ void k_scan() {
    __shared__ int part[1024];
    const int CH = (NODES + 1023) / 1024;  // 98
    int tid = threadIdx.x;
    int s0 = tid * CH;
    int s1 = s0 + CH; if (s1 > NODES) s1 = NODES; if (s0 > NODES) s0 = NODES;
    int sum = 0;
    for (int i = s0; i < s1; i++) sum += d_icnt[i];
    part[tid] = sum;
    __syncthreads();
    for (int off = 1; off < 1024; off <<= 1) {
        int v = (tid >= off) ? part[tid - off] : 0;
        __syncthreads();
        part[tid] += v;
        __syncthreads();
    }
    int run = (tid > 0) ? part[tid - 1] : 0;
    for (int i = s0; i < s1; i++) { d_rowptr[i] = run; run += d_icnt[i]; }
    if (tid == 1023) d_rowptr[NODES] = part[1023];
}

__global__ void k_init(const float* __restrict__ feat) {
    int i = blockIdx.x * blockDim.x + threadIdx.x;
    if (i < NODES) {
        float di = rsqrtf((float)(d_icnt[i] + 1));   // +1 self-loop, always >= 1
        float dq = rsqrtf((float)(d_ocnt[i] + 1));
        d_din[i] = di;
        d_dout[i] = dq;
        d_cursor[i] = d_rowptr[i];
        d_g0[i] = feat[i] * dq;                      // layer-0 source values (scalar)
    }
}

__global__ void k_scatter(const int* __restrict__ src, const int* __restrict__ dst) {
    int e = blockIdx.x * blockDim.x + threadIdx.x;
    if (e < NEDGES) {
        int p = atomicAdd(&d_cursor[dst[e]], 1);
        d_col[p] = src[e];
    }
}

// ---------------- layer 0 : scalar aggregation, D_in = 1 ----------------
__global__ void k_layer0(const float* __restrict__ W, const float* __restrict__ b) {
    const unsigned FULL = 0xffffffffu;
    int lane = threadIdx.x & 31;
    int w    = (blockIdx.x * blockDim.x + threadIdx.x) >> 5;
    int nw   = (gridDim.x * blockDim.x) >> 5;
    int tt   = lane < DD ? lane : 0;
    float wt = W[tt];
    float bt = b[tt];
    for (int n = w; n < NODES; n += nw) {
        int beg = d_rowptr[n], end = d_rowptr[n + 1];
        float acc = (lane == 0) ? d_g0[n] : 0.f;     // self-loop
        for (int j = beg + lane; j < end; j += 32)
            acc += __ldg(&d_g0[__ldg(&d_col[j])]);
        #pragma unroll
        for (int off = 16; off; off >>= 1)
            acc += __shfl_xor_sync(FULL, acc, off);
        if (lane < DD) {
            float r = fmaf(d_din[n] * acc, wt, bt);
            r = fmaxf(r, 0.f);
            d_gA[n * DD + lane] = r * d_dout[n];     // store g = h * dout
        }
    }
}

// ---------------- fused layer: aggregate(g) -> @W -> *din +b -> (relu) -> (*dout) ----
template <int RELU, int SCALE>
__device__ __forceinline__ void layer_body(const float* __restrict__ gin,
                                           float* __restrict__ gout,
                                           const float* __restrict__ W,
                                           const float* __restrict__ b) {
    const unsigned FULL = 0xffffffffu;
    int lane = threadIdx.x & 31;
    int w    = (blockIdx.x * blockDim.x + threadIdx.x) >> 5;
    int nw   = (gridDim.x * blockDim.x) >> 5;
    // lane layout for aggregation: 6 edges x 5 float4 chunks (lanes 30,31 idle)
    int c    = lane % 5;
    int esub = lane / 5;
    bool lok = lane < 30;
    // W column for matvec, loaded ONCE per warp lifetime (grid-stride amortizes it)
    int tt = lane < DD ? lane : 0;
    float wcol[DD];
    #pragma unroll
    for (int k = 0; k < DD; k++) wcol[k] = W[k * DD + tt];
    float bt = b[tt];
    const float4* gin4 = (const float4*)gin;

    for (int n = w; n < NODES; n += nw) {
        int beg = d_rowptr[n], end = d_rowptr[n + 1];
        float4 acc  = make_float4(0.f, 0.f, 0.f, 0.f);
        float4 acc2 = make_float4(0.f, 0.f, 0.f, 0.f);
        if (lok && esub == 0) acc = __ldg(&gin4[n * 5 + c]);   // self-loop

        // ---- software-pipelined main loop: 24 edges / body, 4 rows in flight/lane ----
        int j0 = beg;
        if (lok) {
            for (; j0 + 24 <= end; j0 += 24) {
                int jj = j0 + esub;
                int s0 = __ldg(&d_col[jj]);
                int s1 = __ldg(&d_col[jj + 6]);
                int s2 = __ldg(&d_col[jj + 12]);
                int s3 = __ldg(&d_col[jj + 18]);
                float4 x0 = __ldg(&gin4[s0 * 5 + c]);
                float4 x1 = __ldg(&gin4[s1 * 5 + c]);
                float4 x2 = __ldg(&gin4[s2 * 5 + c]);
                float4 x3 = __ldg(&gin4[s3 * 5 + c]);
                acc.x  += x0.x; acc.y  += x0.y; acc.z  += x0.z; acc.w  += x0.w;
                acc2.x += x1.x; acc2.y += x1.y; acc2.z += x1.z; acc2.w += x1.w;
                acc.x  += x2.x; acc.y  += x2.y; acc.z  += x2.z; acc.w  += x2.w;
                acc2.x += x3.x; acc2.y += x3.y; acc2.z += x3.z; acc2.w += x3.w;
            }
        } else {
            j0 = end - ((end - beg) % 24);           // keep j0 warp-consistent for lanes 30,31
            if (j0 < beg) j0 = beg;
        }
        // NOTE: lanes 30,31 are inactive (lok==false); j0 value only needs to be
        // loop-exit-consistent, handled above.

        // ---- remainder: up to 23 edges, predicated, unroll 2 ----
        #pragma unroll 2
        for (; j0 < end; j0 += 6) {
            int j = j0 + esub;
            if (lok && j < end) {
                int s = __ldg(&d_col[j]);
                float4 x = __ldg(&gin4[s * 5 + c]);
                acc.x += x.x; acc.y += x.y; acc.z += x.z; acc.w += x.w;
            }
        }
        acc.x += acc2.x; acc.y += acc2.y; acc.z += acc2.z; acc.w += acc2.w;

        // Reduce the 6 edge groups (stride 5). Predicated folds so already-consumed
        // lanes are never updated again (avoids double-count contamination):
        //   step1: lanes 0..14  += lanes 15..29   (g_i += g_{i+3})
        //   step2: lanes 0..4   += lanes 10..14   (clean g2+g5)
        //   step3: lanes 0..4   += lanes 5..9     (clean g1+g4, untouched by step2)
        float4 t;
        t.x = __shfl_down_sync(FULL, acc.x, 15);
        t.y = __shfl_down_sync(FULL, acc.y, 15);
        t.z = __shfl_down_sync(FULL, acc.z, 15);
        t.w = __shfl_down_sync(FULL, acc.w, 15);
        if (lane < 15) { acc.x += t.x; acc.y += t.y; acc.z += t.z; acc.w += t.w; }
        t.x = __shfl_down_sync(FULL, acc.x, 10);
        t.y = __shfl_down_sync(FULL, acc.y, 10);
        t.z = __shfl_down_sync(FULL, acc.z, 10);
        t.w = __shfl_down_sync(FULL, acc.w, 10);
        if (lane < 5) { acc.x += t.x; acc.y += t.y; acc.z += t.z; acc.w += t.w; }
        t.x = __shfl_down_sync(FULL, acc.x, 5);
        t.y = __shfl_down_sync(FULL, acc.y, 5);
        t.z = __shfl_down_sync(FULL, acc.z, 5);
        t.w = __shfl_down_sync(FULL, acc.w, 5);
        if (lane < 5) { acc.x += t.x; acc.y += t.y; acc.z += t.z; acc.w += t.w; }

        // lane c (c=0..4) holds s[4c..4c+3]; broadcast + matvec out[tt] = sum_k s[k]*W[k][tt]
        // (k is compile-time constant in the unrolled loop, so the 4-way select is free)
        float m = 0.f;
        #pragma unroll
        for (int k = 0; k < DD; k++) {
            float comp = ((k & 3) == 0) ? acc.x :
                         ((k & 3) == 1) ? acc.y :
                         ((k & 3) == 2) ? acc.z : acc.w;
            float sk = __shfl_sync(FULL, comp, k >> 2);
            m = fmaf(sk, wcol[k], m);
        }
        if (lane < DD) {
            float r = fmaf(d_din[n], m, bt);
            if (RELU)  r = fmaxf(r, 0.f);
            if (SCALE) r *= d_dout[n];
            gout[n * DD + lane] = r;
        }
    }
}

__global__ void __launch_bounds__(256, 4)
k_layer_mid(const float* __restrict__ W, const float* __restrict__ b, int cur) {
    const float* gin = cur ? d_gB : d_gA;
    float* gout      = cur ? d_gA : d_gB;
    layer_body<1, 1>(gin, gout, W, b);
}

__global__ void __launch_bounds__(256, 4)
k_layer_final(const float* __restrict__ W, const float* __restrict__ b,
              int cur, float* __restrict__ out) {
    const float* gin = cur ? d_gB : d_gA;
    layer_body<0, 0>(gin, out, W, b);
}

// ---------------- launch ----------------
extern "C" void kernel_launch(void* const* d_in, const int* in_sizes, int n_in,
                              void* d_out, int out_size) {
    const float* feat = (const float*)d_in[0];
    const float* Ws   = (const float*)d_in[1];
    const float* bs   = (const float*)d_in[2];
    const float* Wm   = (const float*)d_in[3];
    const float* bm   = (const float*)d_in[4];
    const float* Wf   = (const float*)d_in[5];
    const float* bf   = (const float*)d_in[6];
    const int*   src  = (const int*)d_in[7];
    const int*   dst  = (const int*)d_in[8];
    float* out = (float*)d_out;

    // graph build (per-launch; CSR grouped by dst, self-loops kept implicit)
    k_zero   <<<(NODES  + 255) / 256, 256>>>();
    k_hist   <<<(NEDGES + 255) / 256, 256>>>(src, dst);
    k_scan   <<<1, 1024>>>();
    k_init   <<<(NODES  + 255) / 256, 256>>>(feat);
    k_scatter<<<(NEDGES + 255) / 256, 256>>>(src, dst);

    // 20 conv layers, one fused kernel each
    k_layer0<<<592, 256>>>(Ws, bs);                  // writes d_gA
    int cur = 0;                                      // 0: current in gA
    for (int k = 0; k < 18; k++) {
        k_layer_mid<<<592, 256>>>(Wm + k * DD * DD, bm + k * DD, cur);
        cur ^= 1;
    }
    k_layer_final<<<592, 256>>>(Wf, bf, cur, out);
}